// round 4
// baseline (speedup 1.0000x reference)
#include <cuda_runtime.h>
#include <cuda_bf16.h>

// MoE combine: out[token_idx[r]] += gates[r] * expert_hidden[r]
// CSR-lite buckets -> per-token gather -> single coalesced write.
// R4: combine loop reverted to the proven R2 structure (MLP-4, high
// occupancy). Launch-count reduction kept: self-cleaning g_count (no
// zero kernel) + tiny trailing overflow-counter reset.

#define MAX_TOKENS 16384
#define MAX_ROWS   32768
#define CAP        32
#define CTHREADS   256
#define VPT        4   // float4 columns per thread

// Zero-initialized at module load; combine self-cleans g_count and the
// trailing kernel resets g_ovf_count, so every kernel_launch invocation
// (including graph replays) sees zeroed state. Deterministic.
__device__ int g_count[MAX_TOKENS];
__device__ int g_bucket[MAX_TOKENS * CAP];
__device__ int g_ovf_count;
__device__ int g_ovf_rows[MAX_ROWS];

__global__ void bucket_kernel(const int* __restrict__ token_idx, int num_rows) {
    int r = blockIdx.x * blockDim.x + threadIdx.x;
    if (r >= num_rows) return;
    int t = token_idx[r];
    int p = atomicAdd(&g_count[t], 1);
    if (p < CAP) {
        g_bucket[t * CAP + p] = r;
    } else {
        int q = atomicAdd(&g_ovf_count, 1);
        g_ovf_rows[q] = r;
    }
}

// One block per token. Each thread owns VPT float4 columns, strided by
// blockDim so all loads/stores stay fully coalesced. Per bucket row we
// issue VPT independent loads back-to-back -> MLP >= VPT, while keeping
// register pressure low enough for full occupancy (the R3 x2-unroll
// variant regressed 100us by halving resident warps).
__global__ __launch_bounds__(CTHREADS)
void combine_kernel(const float* __restrict__ expert_hidden,
                    const int*   __restrict__ token_idx,
                    const float* __restrict__ gates,
                    float* __restrict__ out,
                    int hidden4) {
    const int t = blockIdx.x;
    __shared__ int   s_rows[CAP];
    __shared__ float s_gates[CAP];
    __shared__ int   s_n;

    if (threadIdx.x == 0) {
        s_n = g_count[t];
        g_count[t] = 0;   // self-clean for the next launch / graph replay
    }
    __syncthreads();
    const int n = s_n;
    const int m = (n < CAP) ? n : CAP;

    if (threadIdx.x < m) {
        int r = g_bucket[t * CAP + threadIdx.x];
        s_rows[threadIdx.x]  = r;
        s_gates[threadIdx.x] = gates[r];
    }
    __syncthreads();

    const float4* eh4  = reinterpret_cast<const float4*>(expert_hidden);
    float4*       out4 = reinterpret_cast<float4*>(out);

    for (int tile = 0; tile < hidden4; tile += VPT * CTHREADS) {
        int col[VPT];
        bool ok[VPT];
        #pragma unroll
        for (int j = 0; j < VPT; j++) {
            col[j] = tile + threadIdx.x + j * CTHREADS;
            ok[j]  = col[j] < hidden4;
        }

        float4 acc[VPT];
        #pragma unroll
        for (int j = 0; j < VPT; j++) acc[j] = make_float4(0.f, 0.f, 0.f, 0.f);

        for (int i = 0; i < m; i++) {
            const long long rb = (long long)s_rows[i] * hidden4;
            const float g = s_gates[i];
            float4 v[VPT];
            #pragma unroll
            for (int j = 0; j < VPT; j++)
                if (ok[j]) v[j] = __ldcs(&eh4[rb + col[j]]);
            #pragma unroll
            for (int j = 0; j < VPT; j++) {
                if (ok[j]) {
                    acc[j].x += g * v[j].x;
                    acc[j].y += g * v[j].y;
                    acc[j].z += g * v[j].z;
                    acc[j].w += g * v[j].w;
                }
            }
        }

        // Exact overflow handling (normally dead: requires a token with >32
        // rows; g_ovf_count is reset only by the trailing kernel, after this
        // kernel completes, so no race).
        if (n > CAP) {
            int q = g_ovf_count;
            for (int jj = 0; jj < q; jj++) {
                int r = g_ovf_rows[jj];
                if (token_idx[r] == t) {
                    float g = gates[r];
                    long long rb = (long long)r * hidden4;
                    #pragma unroll
                    for (int j = 0; j < VPT; j++) {
                        if (ok[j]) {
                            float4 v = eh4[rb + col[j]];
                            acc[j].x += g * v.x;
                            acc[j].y += g * v.y;
                            acc[j].z += g * v.z;
                            acc[j].w += g * v.w;
                        }
                    }
                }
            }
        }

        const long long ob = (long long)t * hidden4;
        #pragma unroll
        for (int j = 0; j < VPT; j++)
            if (ok[j]) __stcs(&out4[ob + col[j]], acc[j]);
    }
}

// Reset the overflow counter AFTER combine so the (normally dead) overflow
// read in combine can never race the reset.
__global__ void reset_ovf_kernel() {
    if (threadIdx.x == 0 && blockIdx.x == 0) g_ovf_count = 0;
}

extern "C" void kernel_launch(void* const* d_in, const int* in_sizes, int n_in,
                              void* d_out, int out_size) {
    const float* expert_hidden = (const float*)d_in[0];
    const int*   token_idx     = (const int*)d_in[1];
    const float* gates         = (const float*)d_in[2];
    float*       out           = (float*)d_out;

    const int num_rows   = in_sizes[1];               // 32768
    const int hidden     = in_sizes[0] / num_rows;    // 4096
    const int num_tokens = out_size / hidden;         // 16384
    const int hidden4    = hidden / 4;

    bucket_kernel<<<(num_rows + 255) / 256, 256>>>(token_idx, num_rows);
    combine_kernel<<<num_tokens, CTHREADS>>>(expert_hidden, token_idx, gates, out, hidden4);
    reset_ovf_kernel<<<1, 32>>>();
}

// round 5
// speedup vs baseline: 1.8677x; 1.8677x over previous
#include <cuda_runtime.h>
#include <cuda_bf16.h>

// MoE combine: out[token_idx[r]] += gates[r] * expert_hidden[r]
// CSR-lite buckets (CAP + exact overflow list) -> per-token gather ->
// single coalesced write. R5: exact revert to the R2 configuration
// (zero kernel + bucket + MLP-4 combine) that measured 129.2us, as a
// controlled A/B against the R3/R4 self-cleaning variants (229/242us).

#define MAX_TOKENS 16384
#define MAX_ROWS   32768
#define CAP        32
#define CTHREADS   256
#define VPT        4   // float4 columns per thread

__device__ int g_count[MAX_TOKENS];
__device__ int g_bucket[MAX_TOKENS * CAP];
__device__ int g_ovf_count;
__device__ int g_ovf_rows[MAX_ROWS];

__global__ void zero_counts_kernel(int num_tokens) {
    int i = blockIdx.x * blockDim.x + threadIdx.x;
    if (i < num_tokens) g_count[i] = 0;
    if (i == 0) g_ovf_count = 0;
}

__global__ void bucket_kernel(const int* __restrict__ token_idx, int num_rows) {
    int r = blockIdx.x * blockDim.x + threadIdx.x;
    if (r >= num_rows) return;
    int t = token_idx[r];
    int p = atomicAdd(&g_count[t], 1);
    if (p < CAP) {
        g_bucket[t * CAP + p] = r;
    } else {
        int q = atomicAdd(&g_ovf_count, 1);
        g_ovf_rows[q] = r;
    }
}

// One block per token. Each thread owns VPT float4 columns, strided by
// blockDim so all loads/stores stay fully coalesced. Per bucket row we
// issue VPT independent loads back-to-back -> MLP >= VPT.
__global__ __launch_bounds__(CTHREADS)
void combine_kernel(const float* __restrict__ expert_hidden,
                    const int*   __restrict__ token_idx,
                    const float* __restrict__ gates,
                    float* __restrict__ out,
                    int hidden4) {
    const int t = blockIdx.x;
    __shared__ int   s_rows[CAP];
    __shared__ float s_gates[CAP];
    __shared__ int   s_n;

    if (threadIdx.x == 0) s_n = g_count[t];
    __syncthreads();
    const int n = s_n;
    const int m = (n < CAP) ? n : CAP;

    if (threadIdx.x < m) {
        int r = g_bucket[t * CAP + threadIdx.x];
        s_rows[threadIdx.x]  = r;
        s_gates[threadIdx.x] = gates[r];
    }
    __syncthreads();

    const float4* eh4  = reinterpret_cast<const float4*>(expert_hidden);
    float4*       out4 = reinterpret_cast<float4*>(out);

    for (int tile = 0; tile < hidden4; tile += VPT * CTHREADS) {
        int col[VPT];
        bool ok[VPT];
        #pragma unroll
        for (int j = 0; j < VPT; j++) {
            col[j] = tile + threadIdx.x + j * CTHREADS;
            ok[j]  = col[j] < hidden4;
        }

        float4 acc[VPT];
        #pragma unroll
        for (int j = 0; j < VPT; j++) acc[j] = make_float4(0.f, 0.f, 0.f, 0.f);

        for (int i = 0; i < m; i++) {
            const long long rb = (long long)s_rows[i] * hidden4;
            const float g = s_gates[i];
            float4 v[VPT];
            #pragma unroll
            for (int j = 0; j < VPT; j++)
                if (ok[j]) v[j] = __ldcs(&eh4[rb + col[j]]);
            #pragma unroll
            for (int j = 0; j < VPT; j++) {
                if (ok[j]) {
                    acc[j].x += g * v[j].x;
                    acc[j].y += g * v[j].y;
                    acc[j].z += g * v[j].z;
                    acc[j].w += g * v[j].w;
                }
            }
        }

        // Exact overflow handling (normally dead: bucket overflow ~ never)
        if (n > CAP) {
            int q = g_ovf_count;
            for (int jj = 0; jj < q; jj++) {
                int r = g_ovf_rows[jj];
                if (token_idx[r] == t) {
                    float g = gates[r];
                    long long rb = (long long)r * hidden4;
                    #pragma unroll
                    for (int j = 0; j < VPT; j++) {
                        if (ok[j]) {
                            float4 v = eh4[rb + col[j]];
                            acc[j].x += g * v.x;
                            acc[j].y += g * v.y;
                            acc[j].z += g * v.z;
                            acc[j].w += g * v.w;
                        }
                    }
                }
            }
        }

        const long long ob = (long long)t * hidden4;
        #pragma unroll
        for (int j = 0; j < VPT; j++)
            if (ok[j]) __stcs(&out4[ob + col[j]], acc[j]);
    }
}

extern "C" void kernel_launch(void* const* d_in, const int* in_sizes, int n_in,
                              void* d_out, int out_size) {
    const float* expert_hidden = (const float*)d_in[0];
    const int*   token_idx     = (const int*)d_in[1];
    const float* gates         = (const float*)d_in[2];
    float*       out           = (float*)d_out;

    const int num_rows   = in_sizes[1];               // 32768
    const int hidden     = in_sizes[0] / num_rows;    // 4096
    const int num_tokens = out_size / hidden;         // 16384
    const int hidden4    = hidden / 4;

    zero_counts_kernel<<<(num_tokens + 255) / 256, 256>>>(num_tokens);
    bucket_kernel<<<(num_rows + 255) / 256, 256>>>(token_idx, num_rows);
    combine_kernel<<<num_tokens, CTHREADS>>>(expert_hidden, token_idx, gates, out, hidden4);
}

// round 6
// speedup vs baseline: 1.8765x; 1.0047x over previous
#include <cuda_runtime.h>
#include <cuda_bf16.h>

// MoE combine: out[token_idx[r]] += gates[r] * expert_hidden[r]
// CSR-lite buckets (CAP + exact overflow list) -> per-token gather ->
// single coalesced write. R6: R5 structure (zero + bucket + combine,
// proven 129us) with a shape-specialized, predicate-free combine path
// for hidden4 == VPT*CTHREADS. Bookkeeping state is NEVER written by the
// streaming kernel (R3/R4 lesson: self-cleaning counters cost ~110us).

#define MAX_TOKENS 16384
#define MAX_ROWS   32768
#define CAP        32
#define CTHREADS   256
#define VPT        4   // float4 columns per thread

__device__ int g_count[MAX_TOKENS];
__device__ int g_bucket[MAX_TOKENS * CAP];
__device__ int g_ovf_count;
__device__ int g_ovf_rows[MAX_ROWS];

__global__ void zero_counts_kernel(int num_tokens) {
    int i = blockIdx.x * blockDim.x + threadIdx.x;
    if (i < num_tokens) g_count[i] = 0;
    if (i == 0) g_ovf_count = 0;
}

__global__ void bucket_kernel(const int* __restrict__ token_idx, int num_rows) {
    int r = blockIdx.x * blockDim.x + threadIdx.x;
    if (r >= num_rows) return;
    int t = token_idx[r];
    int p = atomicAdd(&g_count[t], 1);
    if (p < CAP) {
        g_bucket[t * CAP + p] = r;
    } else {
        int q = atomicAdd(&g_ovf_count, 1);
        g_ovf_rows[q] = r;
    }
}

// Shared prelude: stage bucket rows + gates for token t into smem.
// Returns n (total rows for this token); m = min(n, CAP) rows staged.
__device__ __forceinline__ int stage_bucket(int t,
                                            const float* __restrict__ gates,
                                            int* s_rows, float* s_gates,
                                            int* s_n_ptr) {
    if (threadIdx.x == 0) *s_n_ptr = g_count[t];
    __syncthreads();
    const int n = *s_n_ptr;
    const int m = (n < CAP) ? n : CAP;
    if (threadIdx.x < m) {
        int r = g_bucket[t * CAP + threadIdx.x];
        s_rows[threadIdx.x]  = r;
        s_gates[threadIdx.x] = gates[r];
    }
    __syncthreads();
    return n;
}

// Exact path: hidden4 == VPT*CTHREADS. No predicates, no tile loop.
// Per bucket row: 4 unconditional, address-independent LDG.128s issued
// back-to-back (MLP_p1 = 4), then 16 FFMAs, accumulators in registers.
__global__ __launch_bounds__(CTHREADS)
void combine_exact_kernel(const float* __restrict__ expert_hidden,
                          const int*   __restrict__ token_idx,
                          const float* __restrict__ gates,
                          float* __restrict__ out) {
    const int t = blockIdx.x;
    const int HIDDEN4 = VPT * CTHREADS;   // 1024 float4 columns
    __shared__ int   s_rows[CAP];
    __shared__ float s_gates[CAP];
    __shared__ int   s_n;

    const int n = stage_bucket(t, gates, s_rows, s_gates, &s_n);
    const int m = (n < CAP) ? n : CAP;

    const float4* eh4  = reinterpret_cast<const float4*>(expert_hidden);
    float4*       out4 = reinterpret_cast<float4*>(out);

    const int c0 = threadIdx.x;

    float4 acc[VPT];
    #pragma unroll
    for (int j = 0; j < VPT; j++) acc[j] = make_float4(0.f, 0.f, 0.f, 0.f);

    for (int i = 0; i < m; i++) {
        const long long rb = (long long)s_rows[i] * HIDDEN4;
        const float g = s_gates[i];
        float4 v[VPT];
        #pragma unroll
        for (int j = 0; j < VPT; j++)
            v[j] = __ldcs(&eh4[rb + c0 + j * CTHREADS]);
        #pragma unroll
        for (int j = 0; j < VPT; j++) {
            acc[j].x += g * v[j].x;
            acc[j].y += g * v[j].y;
            acc[j].z += g * v[j].z;
            acc[j].w += g * v[j].w;
        }
    }

    // Exact overflow handling (normally dead: requires a >32-row token).
    if (n > CAP) {
        int q = g_ovf_count;
        for (int jj = 0; jj < q; jj++) {
            int r = g_ovf_rows[jj];
            if (token_idx[r] == t) {
                float g = gates[r];
                long long rb = (long long)r * HIDDEN4;
                #pragma unroll
                for (int j = 0; j < VPT; j++) {
                    float4 v = eh4[rb + c0 + j * CTHREADS];
                    acc[j].x += g * v.x; acc[j].y += g * v.y;
                    acc[j].z += g * v.z; acc[j].w += g * v.w;
                }
            }
        }
    }

    const long long ob = (long long)t * HIDDEN4;
    #pragma unroll
    for (int j = 0; j < VPT; j++)
        __stcs(&out4[ob + c0 + j * CTHREADS], acc[j]);
}

// Generic fallback (any hidden divisible by 4) — identical to R5 combine.
__global__ __launch_bounds__(CTHREADS)
void combine_generic_kernel(const float* __restrict__ expert_hidden,
                            const int*   __restrict__ token_idx,
                            const float* __restrict__ gates,
                            float* __restrict__ out,
                            int hidden4) {
    const int t = blockIdx.x;
    __shared__ int   s_rows[CAP];
    __shared__ float s_gates[CAP];
    __shared__ int   s_n;

    const int n = stage_bucket(t, gates, s_rows, s_gates, &s_n);
    const int m = (n < CAP) ? n : CAP;

    const float4* eh4  = reinterpret_cast<const float4*>(expert_hidden);
    float4*       out4 = reinterpret_cast<float4*>(out);

    for (int tile = 0; tile < hidden4; tile += VPT * CTHREADS) {
        int col[VPT];
        bool ok[VPT];
        #pragma unroll
        for (int j = 0; j < VPT; j++) {
            col[j] = tile + threadIdx.x + j * CTHREADS;
            ok[j]  = col[j] < hidden4;
        }

        float4 acc[VPT];
        #pragma unroll
        for (int j = 0; j < VPT; j++) acc[j] = make_float4(0.f, 0.f, 0.f, 0.f);

        for (int i = 0; i < m; i++) {
            const long long rb = (long long)s_rows[i] * hidden4;
            const float g = s_gates[i];
            float4 v[VPT];
            #pragma unroll
            for (int j = 0; j < VPT; j++)
                if (ok[j]) v[j] = __ldcs(&eh4[rb + col[j]]);
            #pragma unroll
            for (int j = 0; j < VPT; j++) {
                if (ok[j]) {
                    acc[j].x += g * v[j].x;
                    acc[j].y += g * v[j].y;
                    acc[j].z += g * v[j].z;
                    acc[j].w += g * v[j].w;
                }
            }
        }

        if (n > CAP) {
            int q = g_ovf_count;
            for (int jj = 0; jj < q; jj++) {
                int r = g_ovf_rows[jj];
                if (token_idx[r] == t) {
                    float g = gates[r];
                    long long rb = (long long)r * hidden4;
                    #pragma unroll
                    for (int j = 0; j < VPT; j++) {
                        if (ok[j]) {
                            float4 v = eh4[rb + col[j]];
                            acc[j].x += g * v.x; acc[j].y += g * v.y;
                            acc[j].z += g * v.z; acc[j].w += g * v.w;
                        }
                    }
                }
            }
        }

        const long long ob = (long long)t * hidden4;
        #pragma unroll
        for (int j = 0; j < VPT; j++)
            if (ok[j]) __stcs(&out4[ob + col[j]], acc[j]);
    }
}

extern "C" void kernel_launch(void* const* d_in, const int* in_sizes, int n_in,
                              void* d_out, int out_size) {
    const float* expert_hidden = (const float*)d_in[0];
    const int*   token_idx     = (const int*)d_in[1];
    const float* gates         = (const float*)d_in[2];
    float*       out           = (float*)d_out;

    const int num_rows   = in_sizes[1];               // 32768
    const int hidden     = in_sizes[0] / num_rows;    // 4096
    const int num_tokens = out_size / hidden;         // 16384
    const int hidden4    = hidden / 4;

    zero_counts_kernel<<<(num_tokens + 255) / 256, 256>>>(num_tokens);
    bucket_kernel<<<(num_rows + 255) / 256, 256>>>(token_idx, num_rows);

    if (hidden4 == VPT * CTHREADS) {
        combine_exact_kernel<<<num_tokens, CTHREADS>>>(expert_hidden, token_idx,
                                                       gates, out);
    } else {
        combine_generic_kernel<<<num_tokens, CTHREADS>>>(expert_hidden, token_idx,
                                                         gates, out, hidden4);
    }
}

// round 7
// speedup vs baseline: 1.8849x; 1.0045x over previous
#include <cuda_runtime.h>
#include <cuda_bf16.h>

// MoE combine: out[token_idx[r]] += gates[r] * expert_hidden[r]
// CSR-lite buckets (CAP + exact overflow list) -> per-token gather ->
// single coalesced write. R7: same three kernels as the proven 129us
// config, but chained with Programmatic Dependent Launch (PDL) so the
// prelude kernels overlap: bucket's token_idx loads run under zero's
// execution, and combine's launch overlaps bucket's tail.

#define MAX_TOKENS 16384
#define MAX_ROWS   32768
#define CAP        32
#define CTHREADS   256
#define VPT        4   // float4 columns per thread

__device__ int g_count[MAX_TOKENS];
__device__ int g_bucket[MAX_TOKENS * CAP];
__device__ int g_ovf_count;
__device__ int g_ovf_rows[MAX_ROWS];

__device__ __forceinline__ void gdc_wait() {
    asm volatile("griddepcontrol.wait;" ::: "memory");
}
__device__ __forceinline__ void gdc_launch_dependents() {
    asm volatile("griddepcontrol.launch_dependents;" ::: "memory");
}

__global__ void zero_counts_kernel(int num_tokens) {
    int i = blockIdx.x * blockDim.x + threadIdx.x;
    if (i < num_tokens) g_count[i] = 0;
    if (i == 0) g_ovf_count = 0;
    // All zeroing stores issued above -> let the bucket kernel launch.
    gdc_launch_dependents();
}

__global__ void bucket_kernel(const int* __restrict__ token_idx, int num_rows) {
    int r = blockIdx.x * blockDim.x + threadIdx.x;
    // Independent DRAM load issued BEFORE waiting on the zero kernel:
    // overlaps this kernel's memory latency with zero's execution.
    int t = (r < num_rows) ? token_idx[r] : 0;
    gdc_wait();
    if (r < num_rows) {
        int p = atomicAdd(&g_count[t], 1);
        if (p < CAP) {
            g_bucket[t * CAP + p] = r;
        } else {
            int q = atomicAdd(&g_ovf_count, 1);
            g_ovf_rows[q] = r;
        }
    }
    // Bucket writes done -> combine may launch.
    gdc_launch_dependents();
}

// Exact path: hidden4 == VPT*CTHREADS (hidden=4096). Predicate-free,
// MLP-4 loads, register accumulators, single streamed write.
__global__ __launch_bounds__(CTHREADS)
void combine_exact_kernel(const float* __restrict__ expert_hidden,
                          const int*   __restrict__ token_idx,
                          const float* __restrict__ gates,
                          float* __restrict__ out) {
    const int t = blockIdx.x;
    const int HIDDEN4 = VPT * CTHREADS;   // 1024 float4 columns
    __shared__ int   s_rows[CAP];
    __shared__ float s_gates[CAP];
    __shared__ int   s_n;

    // Wait for the bucket kernel's writes to be visible.
    gdc_wait();

    if (threadIdx.x == 0) s_n = g_count[t];
    __syncthreads();
    const int n = s_n;
    const int m = (n < CAP) ? n : CAP;

    if (threadIdx.x < m) {
        int r = g_bucket[t * CAP + threadIdx.x];
        s_rows[threadIdx.x]  = r;
        s_gates[threadIdx.x] = gates[r];
    }
    __syncthreads();

    const float4* eh4  = reinterpret_cast<const float4*>(expert_hidden);
    float4*       out4 = reinterpret_cast<float4*>(out);
    const int c0 = threadIdx.x;

    float4 acc[VPT];
    #pragma unroll
    for (int j = 0; j < VPT; j++) acc[j] = make_float4(0.f, 0.f, 0.f, 0.f);

    for (int i = 0; i < m; i++) {
        const long long rb = (long long)s_rows[i] * HIDDEN4;
        const float g = s_gates[i];
        float4 v[VPT];
        #pragma unroll
        for (int j = 0; j < VPT; j++)
            v[j] = __ldcs(&eh4[rb + c0 + j * CTHREADS]);
        #pragma unroll
        for (int j = 0; j < VPT; j++) {
            acc[j].x += g * v[j].x;
            acc[j].y += g * v[j].y;
            acc[j].z += g * v[j].z;
            acc[j].w += g * v[j].w;
        }
    }

    // Exact overflow handling (normally dead: requires a >32-row token).
    if (n > CAP) {
        int q = g_ovf_count;
        for (int jj = 0; jj < q; jj++) {
            int r = g_ovf_rows[jj];
            if (token_idx[r] == t) {
                float g = gates[r];
                long long rb = (long long)r * HIDDEN4;
                #pragma unroll
                for (int j = 0; j < VPT; j++) {
                    float4 v = eh4[rb + c0 + j * CTHREADS];
                    acc[j].x += g * v.x; acc[j].y += g * v.y;
                    acc[j].z += g * v.z; acc[j].w += g * v.w;
                }
            }
        }
    }

    const long long ob = (long long)t * HIDDEN4;
    #pragma unroll
    for (int j = 0; j < VPT; j++)
        __stcs(&out4[ob + c0 + j * CTHREADS], acc[j]);
}

// Generic fallback (any hidden divisible by 4).
__global__ __launch_bounds__(CTHREADS)
void combine_generic_kernel(const float* __restrict__ expert_hidden,
                            const int*   __restrict__ token_idx,
                            const float* __restrict__ gates,
                            float* __restrict__ out,
                            int hidden4) {
    const int t = blockIdx.x;
    __shared__ int   s_rows[CAP];
    __shared__ float s_gates[CAP];
    __shared__ int   s_n;

    gdc_wait();

    if (threadIdx.x == 0) s_n = g_count[t];
    __syncthreads();
    const int n = s_n;
    const int m = (n < CAP) ? n : CAP;

    if (threadIdx.x < m) {
        int r = g_bucket[t * CAP + threadIdx.x];
        s_rows[threadIdx.x]  = r;
        s_gates[threadIdx.x] = gates[r];
    }
    __syncthreads();

    const float4* eh4  = reinterpret_cast<const float4*>(expert_hidden);
    float4*       out4 = reinterpret_cast<float4*>(out);

    for (int tile = 0; tile < hidden4; tile += VPT * CTHREADS) {
        int col[VPT];
        bool ok[VPT];
        #pragma unroll
        for (int j = 0; j < VPT; j++) {
            col[j] = tile + threadIdx.x + j * CTHREADS;
            ok[j]  = col[j] < hidden4;
        }

        float4 acc[VPT];
        #pragma unroll
        for (int j = 0; j < VPT; j++) acc[j] = make_float4(0.f, 0.f, 0.f, 0.f);

        for (int i = 0; i < m; i++) {
            const long long rb = (long long)s_rows[i] * hidden4;
            const float g = s_gates[i];
            float4 v[VPT];
            #pragma unroll
            for (int j = 0; j < VPT; j++)
                if (ok[j]) v[j] = __ldcs(&eh4[rb + col[j]]);
            #pragma unroll
            for (int j = 0; j < VPT; j++) {
                if (ok[j]) {
                    acc[j].x += g * v[j].x;
                    acc[j].y += g * v[j].y;
                    acc[j].z += g * v[j].z;
                    acc[j].w += g * v[j].w;
                }
            }
        }

        if (n > CAP) {
            int q = g_ovf_count;
            for (int jj = 0; jj < q; jj++) {
                int r = g_ovf_rows[jj];
                if (token_idx[r] == t) {
                    float g = gates[r];
                    long long rb = (long long)r * hidden4;
                    #pragma unroll
                    for (int j = 0; j < VPT; j++) {
                        if (ok[j]) {
                            float4 v = eh4[rb + col[j]];
                            acc[j].x += g * v.x; acc[j].y += g * v.y;
                            acc[j].z += g * v.z; acc[j].w += g * v.w;
                        }
                    }
                }
            }
        }

        const long long ob = (long long)t * hidden4;
        #pragma unroll
        for (int j = 0; j < VPT; j++)
            if (ok[j]) __stcs(&out4[ob + col[j]], acc[j]);
    }
}

extern "C" void kernel_launch(void* const* d_in, const int* in_sizes, int n_in,
                              void* d_out, int out_size) {
    const float* expert_hidden = (const float*)d_in[0];
    const int*   token_idx     = (const int*)d_in[1];
    const float* gates         = (const float*)d_in[2];
    float*       out           = (float*)d_out;

    const int num_rows   = in_sizes[1];               // 32768
    const int hidden     = in_sizes[0] / num_rows;    // 4096
    const int num_tokens = out_size / hidden;         // 16384
    const int hidden4    = hidden / 4;

    // 1) zero counters (plain launch)
    zero_counts_kernel<<<(num_tokens + 255) / 256, 256>>>(num_tokens);

    // PDL attribute: allow the kernel to launch while its stream
    // predecessor is still running; the kernel gates itself with
    // griddepcontrol.wait before consuming the predecessor's writes.
    cudaLaunchAttribute pdl_attr[1];
    pdl_attr[0].id = cudaLaunchAttributeProgrammaticStreamSerialization;
    pdl_attr[0].val.programmaticStreamSerializationAllowed = 1;

    // 2) bucket (PDL after zero)
    {
        cudaLaunchConfig_t cfg = {};
        cfg.gridDim  = dim3((num_rows + 255) / 256);
        cfg.blockDim = dim3(256);
        cfg.stream   = 0;
        cfg.attrs    = pdl_attr;
        cfg.numAttrs = 1;
        cudaLaunchKernelEx(&cfg, bucket_kernel, token_idx, num_rows);
    }

    // 3) combine (PDL after bucket)
    {
        cudaLaunchConfig_t cfg = {};
        cfg.gridDim  = dim3(num_tokens);
        cfg.blockDim = dim3(CTHREADS);
        cfg.stream   = 0;
        cfg.attrs    = pdl_attr;
        cfg.numAttrs = 1;
        if (hidden4 == VPT * CTHREADS) {
            cudaLaunchKernelEx(&cfg, combine_exact_kernel,
                               expert_hidden, token_idx, gates, out);
        } else {
            cudaLaunchKernelEx(&cfg, combine_generic_kernel,
                               expert_hidden, token_idx, gates, out, hidden4);
        }
    }
}

// round 8
// speedup vs baseline: 1.8911x; 1.0032x over previous
#include <cuda_runtime.h>
#include <cuda_bf16.h>

// MoE combine: out[token_idx[r]] += gates[r] * expert_hidden[r]
// CSR-lite buckets -> per-token gather -> single coalesced write.
// R8: combine processes TPB=4 tokens per block with double-buffered
// metadata prefetch, hiding the g_count->g_bucket->gates dependent
// chain under the previous token's streaming. PDL chaining kept.
// Streaming inner loop identical to the proven 128.5us exact path.

#define MAX_TOKENS 16384
#define MAX_ROWS   32768
#define CAP        32
#define CTHREADS   256
#define VPT        4   // float4 columns per thread
#define TPB        4   // tokens per combine block

__device__ int g_count[MAX_TOKENS];
__device__ int g_bucket[MAX_TOKENS * CAP];
__device__ int g_ovf_count;
__device__ int g_ovf_rows[MAX_ROWS];

__device__ __forceinline__ void gdc_wait() {
    asm volatile("griddepcontrol.wait;" ::: "memory");
}
__device__ __forceinline__ void gdc_launch_dependents() {
    asm volatile("griddepcontrol.launch_dependents;" ::: "memory");
}

__global__ void zero_counts_kernel(int num_tokens) {
    int i = blockIdx.x * blockDim.x + threadIdx.x;
    if (i < num_tokens) g_count[i] = 0;
    if (i == 0) g_ovf_count = 0;
    gdc_launch_dependents();
}

__global__ void bucket_kernel(const int* __restrict__ token_idx, int num_rows) {
    int r = blockIdx.x * blockDim.x + threadIdx.x;
    // Independent DRAM load issued BEFORE waiting on the zero kernel.
    int t = (r < num_rows) ? token_idx[r] : 0;
    gdc_wait();
    if (r < num_rows) {
        int p = atomicAdd(&g_count[t], 1);
        if (p < CAP) {
            g_bucket[t * CAP + p] = r;
        } else {
            int q = atomicAdd(&g_ovf_count, 1);
            g_ovf_rows[q] = r;
        }
    }
    gdc_launch_dependents();
}

// ---------------------------------------------------------------------------
// Streaming core for one token (exact shape: hidden4 == VPT*CTHREADS).
// Predicate-free, MLP-4 back-to-back LDG.128, register accumulators.
// ---------------------------------------------------------------------------
__device__ __forceinline__ void stream_token(int t, int n,
                                             const int*   s_rows,
                                             const float* s_gates,
                                             const float4* __restrict__ eh4,
                                             const int*    __restrict__ token_idx,
                                             const float*  __restrict__ gates,
                                             float4*       __restrict__ out4) {
    const int HIDDEN4 = VPT * CTHREADS;   // 1024 float4 columns
    const int c0 = threadIdx.x;
    const int m  = (n < CAP) ? n : CAP;

    float4 acc[VPT];
    #pragma unroll
    for (int j = 0; j < VPT; j++) acc[j] = make_float4(0.f, 0.f, 0.f, 0.f);

    for (int i = 0; i < m; i++) {
        const long long rb = (long long)s_rows[i] * HIDDEN4;
        const float g = s_gates[i];
        float4 v[VPT];
        #pragma unroll
        for (int j = 0; j < VPT; j++)
            v[j] = __ldcs(&eh4[rb + c0 + j * CTHREADS]);
        #pragma unroll
        for (int j = 0; j < VPT; j++) {
            acc[j].x += g * v[j].x;
            acc[j].y += g * v[j].y;
            acc[j].z += g * v[j].z;
            acc[j].w += g * v[j].w;
        }
    }

    // Exact overflow handling (normally dead: requires a >32-row token).
    if (n > CAP) {
        int q = g_ovf_count;
        for (int jj = 0; jj < q; jj++) {
            int r = g_ovf_rows[jj];
            if (token_idx[r] == t) {
                float g = gates[r];
                long long rb = (long long)r * HIDDEN4;
                #pragma unroll
                for (int j = 0; j < VPT; j++) {
                    float4 v = eh4[rb + c0 + j * CTHREADS];
                    acc[j].x += g * v.x; acc[j].y += g * v.y;
                    acc[j].z += g * v.z; acc[j].w += g * v.w;
                }
            }
        }
    }

    const long long ob = (long long)t * HIDDEN4;
    #pragma unroll
    for (int j = 0; j < VPT; j++)
        __stcs(&out4[ob + c0 + j * CTHREADS], acc[j]);
}

// Combine: TPB tokens per block, double-buffered metadata prefetch.
// Tokens strided: t = blockIdx.x + k * gridDim.x.
__global__ __launch_bounds__(CTHREADS)
void combine_multi_kernel(const float* __restrict__ expert_hidden,
                          const int*   __restrict__ token_idx,
                          const float* __restrict__ gates,
                          float* __restrict__ out) {
    __shared__ int   s_rows[2][CAP];
    __shared__ float s_gates[2][CAP];
    __shared__ int   s_n[2];

    gdc_wait();

    const int nblock = gridDim.x;
    const int t0 = blockIdx.x;

    // Load metadata for token k=0 directly into buffer 0.
    // Note: bucket slots >= count hold stale in-range values; never used
    // in math (m bounds the loop), so reads are safe + deterministic.
    {
        int t = t0;
        if (threadIdx.x == 0) s_n[0] = g_count[t];
        if (threadIdx.x < CAP) {
            int r = g_bucket[t * CAP + threadIdx.x];
            s_rows[0][threadIdx.x]  = r;
            s_gates[0][threadIdx.x] = gates[r];
        }
    }
    __syncthreads();

    const float4* eh4  = reinterpret_cast<const float4*>(expert_hidden);
    float4*       out4 = reinterpret_cast<float4*>(out);

    #pragma unroll
    for (int k = 0; k < TPB; k++) {
        const int buf  = k & 1;
        const int nbuf = buf ^ 1;
        const int t    = t0 + k * nblock;

        // Issue next token's metadata loads NOW (consumed after streaming):
        // their DRAM latency hides under the current token's stream.
        int   pn = 0, pr = 0;
        float pg = 0.f;
        const bool hasnext = (k + 1 < TPB);
        if (hasnext) {
            const int tn = t0 + (k + 1) * nblock;
            if (threadIdx.x == 0) pn = g_count[tn];
            if (threadIdx.x < CAP) {
                pr = g_bucket[tn * CAP + threadIdx.x];
                pg = gates[pr];
            }
        }

        // Stream the current token (the long, bandwidth-bound part).
        stream_token(t, s_n[buf], s_rows[buf], s_gates[buf],
                     eh4, token_idx, gates, out4);

        // Publish prefetched metadata for the next iteration.
        if (hasnext) {
            if (threadIdx.x == 0) s_n[nbuf] = pn;
            if (threadIdx.x < CAP) {
                s_rows[nbuf][threadIdx.x]  = pr;
                s_gates[nbuf][threadIdx.x] = pg;
            }
            __syncthreads();
        }
    }
}

// Generic fallback (any hidden divisible by 4), one token per block.
__global__ __launch_bounds__(CTHREADS)
void combine_generic_kernel(const float* __restrict__ expert_hidden,
                            const int*   __restrict__ token_idx,
                            const float* __restrict__ gates,
                            float* __restrict__ out,
                            int hidden4) {
    const int t = blockIdx.x;
    __shared__ int   s_rows[CAP];
    __shared__ float s_gates[CAP];
    __shared__ int   s_n;

    gdc_wait();

    if (threadIdx.x == 0) s_n = g_count[t];
    __syncthreads();
    const int n = s_n;
    const int m = (n < CAP) ? n : CAP;

    if (threadIdx.x < m) {
        int r = g_bucket[t * CAP + threadIdx.x];
        s_rows[threadIdx.x]  = r;
        s_gates[threadIdx.x] = gates[r];
    }
    __syncthreads();

    const float4* eh4  = reinterpret_cast<const float4*>(expert_hidden);
    float4*       out4 = reinterpret_cast<float4*>(out);

    for (int tile = 0; tile < hidden4; tile += VPT * CTHREADS) {
        int col[VPT];
        bool ok[VPT];
        #pragma unroll
        for (int j = 0; j < VPT; j++) {
            col[j] = tile + threadIdx.x + j * CTHREADS;
            ok[j]  = col[j] < hidden4;
        }
        float4 acc[VPT];
        #pragma unroll
        for (int j = 0; j < VPT; j++) acc[j] = make_float4(0.f, 0.f, 0.f, 0.f);

        for (int i = 0; i < m; i++) {
            const long long rb = (long long)s_rows[i] * hidden4;
            const float g = s_gates[i];
            float4 v[VPT];
            #pragma unroll
            for (int j = 0; j < VPT; j++)
                if (ok[j]) v[j] = __ldcs(&eh4[rb + col[j]]);
            #pragma unroll
            for (int j = 0; j < VPT; j++) {
                if (ok[j]) {
                    acc[j].x += g * v[j].x; acc[j].y += g * v[j].y;
                    acc[j].z += g * v[j].z; acc[j].w += g * v[j].w;
                }
            }
        }

        if (n > CAP) {
            int q = g_ovf_count;
            for (int jj = 0; jj < q; jj++) {
                int r = g_ovf_rows[jj];
                if (token_idx[r] == t) {
                    float g = gates[r];
                    long long rb = (long long)r * hidden4;
                    #pragma unroll
                    for (int j = 0; j < VPT; j++) {
                        if (ok[j]) {
                            float4 v = eh4[rb + col[j]];
                            acc[j].x += g * v.x; acc[j].y += g * v.y;
                            acc[j].z += g * v.z; acc[j].w += g * v.w;
                        }
                    }
                }
            }
        }

        const long long ob = (long long)t * hidden4;
        #pragma unroll
        for (int j = 0; j < VPT; j++)
            if (ok[j]) __stcs(&out4[ob + col[j]], acc[j]);
    }
}

extern "C" void kernel_launch(void* const* d_in, const int* in_sizes, int n_in,
                              void* d_out, int out_size) {
    const float* expert_hidden = (const float*)d_in[0];
    const int*   token_idx     = (const int*)d_in[1];
    const float* gates         = (const float*)d_in[2];
    float*       out           = (float*)d_out;

    const int num_rows   = in_sizes[1];               // 32768
    const int hidden     = in_sizes[0] / num_rows;    // 4096
    const int num_tokens = out_size / hidden;         // 16384
    const int hidden4    = hidden / 4;

    zero_counts_kernel<<<(num_tokens + 255) / 256, 256>>>(num_tokens);

    cudaLaunchAttribute pdl_attr[1];
    pdl_attr[0].id = cudaLaunchAttributeProgrammaticStreamSerialization;
    pdl_attr[0].val.programmaticStreamSerializationAllowed = 1;

    {
        cudaLaunchConfig_t cfg = {};
        cfg.gridDim  = dim3((num_rows + 255) / 256);
        cfg.blockDim = dim3(256);
        cfg.stream   = 0;
        cfg.attrs    = pdl_attr;
        cfg.numAttrs = 1;
        cudaLaunchKernelEx(&cfg, bucket_kernel, token_idx, num_rows);
    }

    {
        cudaLaunchConfig_t cfg = {};
        cfg.blockDim = dim3(CTHREADS);
        cfg.stream   = 0;
        cfg.attrs    = pdl_attr;
        cfg.numAttrs = 1;
        if (hidden4 == VPT * CTHREADS && (num_tokens % TPB) == 0) {
            cfg.gridDim = dim3(num_tokens / TPB);
            cudaLaunchKernelEx(&cfg, combine_multi_kernel,
                               expert_hidden, token_idx, gates, out);
        } else {
            cfg.gridDim = dim3(num_tokens);
            cudaLaunchKernelEx(&cfg, combine_generic_kernel,
                               expert_hidden, token_idx, gates, out, hidden4);
        }
    }
}